// round 16
// baseline (speedup 1.0000x reference)
#include <cuda_runtime.h>
#include <cuda_fp16.h>
#include <math.h>
#include <stdint.h>

#define CIN   128
#define COUTB 256
#define HW    384
#define LPOS  16384
#define NB    4
#define NTILE 36864            // 192*192 winograd tiles per image
#define NCO   384              // fused couts

// ---------------- static device scratch ----------------
__device__ __align__(16) float  g_part[(size_t)36 * 2 * 8 * 128 * 128];
__device__ __align__(16) __half g_y1h[(size_t)NB * 9 * LPOS * CIN];
__device__ __align__(16) __half g_y1l[(size_t)NB * 9 * LPOS * CIN];
__device__ __align__(16) __half g_y2h[(size_t)NB * 9 * LPOS * COUTB];
__device__ __align__(16) __half g_y2l[(size_t)NB * 9 * LPOS * COUTB];
__device__ __align__(16) __half g_Vh[(size_t)NB * 16 * NTILE * CIN];
__device__ __align__(16) __half g_Vl[(size_t)NB * 16 * NTILE * CIN];
__device__ __align__(16) __half g_Uh[(size_t)16 * NCO * CIN];
__device__ __align__(16) __half g_Ul[(size_t)16 * NCO * CIN];

// ---------------- helpers ----------------
__device__ __forceinline__ uint32_t s2u(const void* p) {
    uint32_t a; asm("{ .reg .u64 t; cvta.to.shared.u64 t, %1; cvt.u32.u64 %0, t; }" : "=r"(a) : "l"(p)); return a;
}
__device__ __forceinline__ void cpa16(uint32_t dst, const void* src) {
    asm volatile("cp.async.cg.shared.global [%0], [%1], 16;" :: "r"(dst), "l"(src));
}
__device__ __forceinline__ void ldm4(uint32_t* r, uint32_t addr) {
    asm volatile("ldmatrix.sync.aligned.m8n8.x4.shared.b16 {%0,%1,%2,%3}, [%4];"
        : "=r"(r[0]), "=r"(r[1]), "=r"(r[2]), "=r"(r[3]) : "r"(addr));
}
__device__ __forceinline__ void ldm4t(uint32_t* r, uint32_t addr) {
    asm volatile("ldmatrix.sync.aligned.m8n8.x4.trans.shared.b16 {%0,%1,%2,%3}, [%4];"
        : "=r"(r[0]), "=r"(r[1]), "=r"(r[2]), "=r"(r[3]) : "r"(addr));
}
__device__ __forceinline__ void mma16816(float* d, const uint32_t* a, const uint32_t* b) {
    asm volatile("mma.sync.aligned.m16n8k16.row.col.f32.f16.f16.f32 "
        "{%0,%1,%2,%3}, {%4,%5,%6,%7}, {%8,%9}, {%0,%1,%2,%3};"
        : "+f"(d[0]), "+f"(d[1]), "+f"(d[2]), "+f"(d[3])
        : "r"(a[0]), "r"(a[1]), "r"(a[2]), "r"(a[3]), "r"(b[0]), "r"(b[1]));
}

// =====================================================================
// K1: weight transform U = G g G^T, fp16 hi + UNSCALED lo limbs. [e][co][ci]
// =====================================================================
__global__ void prep_uw_kernel(const float* __restrict__ w1, const float* __restrict__ w2)
{
    int idx = blockIdx.x * 256 + threadIdx.x;
    if (idx >= NCO * CIN) return;
    int co = idx >> 7, ci = idx & 127;
    const float* src = (co < CIN) ? (w1 + ((size_t)co * CIN + ci) * 9)
                                  : (w2 + ((size_t)(co - CIN) * CIN + ci) * 9);
    float g[3][3];
#pragma unroll
    for (int r = 0; r < 3; r++)
#pragma unroll
        for (int c = 0; c < 3; c++) g[r][c] = src[r * 3 + c];
    float tr[4][3];
#pragma unroll
    for (int c = 0; c < 3; c++) {
        tr[0][c] = g[0][c];
        tr[1][c] = 0.5f * (g[0][c] + g[1][c] + g[2][c]);
        tr[2][c] = 0.5f * (g[0][c] - g[1][c] + g[2][c]);
        tr[3][c] = g[2][c];
    }
#pragma unroll
    for (int r = 0; r < 4; r++) {
        float uu[4];
        uu[0] = tr[r][0];
        uu[1] = 0.5f * (tr[r][0] + tr[r][1] + tr[r][2]);
        uu[2] = 0.5f * (tr[r][0] - tr[r][1] + tr[r][2]);
        uu[3] = tr[r][2];
#pragma unroll
        for (int c = 0; c < 4; c++) {
            int e = r * 4 + c;
            __half hi = __float2half_rn(uu[c]);
            g_Uh[(size_t)e * (NCO * CIN) + idx] = hi;
            g_Ul[(size_t)e * (NCO * CIN) + idx] = __float2half_rn(uu[c] - __half2float(hi));
        }
    }
}

// =====================================================================
// K2: input transform V = B^T d B per 4x4 window (stride 2, pad 1).
// Block: 16 tiles x 64 ci; each thread owns an adjacent ci PAIR and
// writes __half2 (full 128B warp sectors on the 1.2GB of V stores).
// grid (12, 192, 8): z = cic(2) + b*2.
// =====================================================================
__global__ void transform_x_kernel(const float* __restrict__ x)
{
    __shared__ float st[4][34][67];     // [r][c][ci]; 67 pad -> 3c mod 32 banks
    const int bx = blockIdx.x;          // 0..11, 16 tiles each
    const int ty = blockIdx.y;          // 0..191
    const int cic = blockIdx.z & 1, b = blockIdx.z >> 1;
    const int t = threadIdx.x, l = t & 31, wrp = t >> 5;

    // load 64 ci x 4 rows x 34 cols (one (ci,r) row per warp-iter, coalesced)
    for (int rr = wrp; rr < 256; rr += 8) {
        int ci_l = rr >> 2, r = rr & 3;
        const float* xp = x + ((size_t)(b * CIN + cic * 64 + ci_l)) * HW * HW;
        int h = 2 * ty - 1 + r;
#pragma unroll
        for (int cc = 0; cc < 2; cc++) {
            int c = cc * 32 + l;
            if (c < 34) {
                int w = bx * 32 - 1 + c;
                float v = 0.f;
                if ((unsigned)h < HW && (unsigned)w < HW) v = xp[(size_t)h * HW + w];
                st[r][c][ci_l] = v;
            }
        }
    }
    __syncthreads();

    const int cip = t & 31, tl = t >> 5;   // ci-pair 0..31, tile-lane 0..7
    const int ci0 = 2 * cip;
#pragma unroll
    for (int pass = 0; pass < 2; pass++) {
        int txl = pass * 8 + tl;
        int cb  = 2 * txl;
        float d0[4][4], d1[4][4];
#pragma unroll
        for (int r = 0; r < 4; r++)
#pragma unroll
            for (int c = 0; c < 4; c++) {
                d0[r][c] = st[r][cb + c][ci0];
                d1[r][c] = st[r][cb + c][ci0 + 1];
            }
        float tm0[4][4], tm1[4][4];
#pragma unroll
        for (int c = 0; c < 4; c++) {
            tm0[0][c] = d0[0][c] - d0[2][c];  tm1[0][c] = d1[0][c] - d1[2][c];
            tm0[1][c] = d0[1][c] + d0[2][c];  tm1[1][c] = d1[1][c] + d1[2][c];
            tm0[2][c] = d0[2][c] - d0[1][c];  tm1[2][c] = d1[2][c] - d1[1][c];
            tm0[3][c] = d0[1][c] - d0[3][c];  tm1[3][c] = d1[1][c] - d1[3][c];
        }
        size_t tile = (size_t)ty * 192 + bx * 16 + txl;
#pragma unroll
        for (int r = 0; r < 4; r++) {
            float v0[4], v1[4];
            v0[0] = tm0[r][0] - tm0[r][2];  v1[0] = tm1[r][0] - tm1[r][2];
            v0[1] = tm0[r][1] + tm0[r][2];  v1[1] = tm1[r][1] + tm1[r][2];
            v0[2] = tm0[r][2] - tm0[r][1];  v1[2] = tm1[r][2] - tm1[r][1];
            v0[3] = tm0[r][1] - tm0[r][3];  v1[3] = tm1[r][1] - tm1[r][3];
#pragma unroll
            for (int c = 0; c < 4; c++) {
                int e = r * 4 + c;
                size_t off = ((size_t)(b * 16 + e) * NTILE + tile) * CIN + cic * 64 + ci0;
                __half h0 = __float2half_rn(v0[c]);
                __half h1 = __float2half_rn(v1[c]);
                __half2 hh; hh.x = h0; hh.y = h1;
                *(__half2*)&g_Vh[off] = hh;
                __half2 ll;
                ll.x = __float2half_rn(v0[c] - __half2float(h0));
                ll.y = __float2half_rn(v1[c] - __half2float(h1));
                *(__half2*)&g_Vl[off] = ll;
            }
        }
    }
}

// =====================================================================
// K3: winograd GEMM + fused output transform; single fp32 accumulator
// (unscaled lo limbs -> all 3 products at true scale). UNCHANGED (R14).
// CTA: co 128 x tiles 64, loop e 0..15. 512 thr, 16 warps (4m x 4n).
// =====================================================================
#define W_AL   17408               // halves: 128*136
#define W_BH   34816
#define W_BL   43520
#define W_STG  52224
#define W_SMEM (2 * W_STG * 2)     // 208896 bytes

__global__ void __launch_bounds__(512, 1) wino_gemm_kernel()
{
    extern __shared__ __half sw[];
    const int t = threadIdx.x, l = t & 31, wrp = t >> 5;
    const int mw = wrp & 3, nw = wrp >> 2;
    const int q = l >> 2, tq = l & 3;
    const int tb = blockIdx.x, cob = blockIdx.y, b = blockIdx.z;
    const uint32_t smb = s2u(sw);

    float yac[2][2][4][4];
#pragma unroll
    for (int i = 0; i < 2; i++)
#pragma unroll
        for (int j = 0; j < 2; j++)
#pragma unroll
            for (int d = 0; d < 4; d++)
#pragma unroll
                for (int uv = 0; uv < 4; uv++) yac[i][j][d][uv] = 0.f;

    auto load_e = [&](int e, int buf) {
        const uint32_t base = smb + buf * (W_STG * 2);
        const __half* Uh = g_Uh + (size_t)e * (NCO * CIN) + (size_t)cob * 128 * CIN;
        const __half* Ul = g_Ul + (size_t)e * (NCO * CIN) + (size_t)cob * 128 * CIN;
#pragma unroll
        for (int i = 0; i < 4; i++) {
            int id = t + i * 512;
            int row = id >> 4, kc = id & 15;
            uint32_t o = (row * 136 + kc * 8) * 2;
            cpa16(base + o,            Uh + (size_t)row * CIN + kc * 8);
            cpa16(base + W_AL * 2 + o, Ul + (size_t)row * CIN + kc * 8);
        }
        const __half* Vh = g_Vh + ((size_t)(b * 16 + e) * NTILE + (size_t)tb * 64) * CIN;
        const __half* Vl = g_Vl + ((size_t)(b * 16 + e) * NTILE + (size_t)tb * 64) * CIN;
#pragma unroll
        for (int i = 0; i < 2; i++) {
            int id = t + i * 512;
            int row = id >> 4, kc = id & 15;
            uint32_t o = (row * 136 + kc * 8) * 2;
            cpa16(base + W_BH * 2 + o, Vh + (size_t)row * CIN + kc * 8);
            cpa16(base + W_BL * 2 + o, Vl + (size_t)row * CIN + kc * 8);
        }
        asm volatile("cp.async.commit_group;" ::: "memory");
    };

    const float AT0[4] = {1.f, 1.f, 1.f, 0.f};
    const float AT1[4] = {0.f, 1.f, -1.f, -1.f};

    load_e(0, 0);

#pragma unroll 1
    for (int e = 0; e < 16; e++) {
        const int buf = e & 1;
        if (e < 15) {
            load_e(e + 1, buf ^ 1);
            asm volatile("cp.async.wait_group 1;" ::: "memory");
        } else {
            asm volatile("cp.async.wait_group 0;" ::: "memory");
        }
        __syncthreads();

        const uint32_t base = smb + buf * (W_STG * 2);
        const int r8 = l & 7, tt = l >> 3;

        float m_[2][2][4];
#pragma unroll
        for (int i = 0; i < 2; i++)
#pragma unroll
            for (int j = 0; j < 2; j++)
#pragma unroll
                for (int d = 0; d < 4; d++) m_[i][j][d] = 0.f;

#pragma unroll
        for (int ks = 0; ks < 8; ks++) {
            uint32_t ah[2][4], al[2][4];
#pragma unroll
            for (int i = 0; i < 2; i++) {
                uint32_t arow = mw * 32 + i * 16 + (tt & 1) * 8 + r8;
                uint32_t aoff = arow * 272 + (ks * 16 + (tt >> 1) * 8) * 2;
                ldm4(ah[i], base + aoff);
                ldm4(al[i], base + W_AL * 2 + aoff);
            }
            uint32_t bh4[4], bl4[4];
            {
                uint32_t brow = nw * 16 + (tt >> 1) * 8 + r8;
                uint32_t boff = brow * 272 + (ks * 16 + (tt & 1) * 8) * 2;
                ldm4(bh4, base + W_BH * 2 + boff);
                ldm4(bl4, base + W_BL * 2 + boff);
            }
#pragma unroll
            for (int i = 0; i < 2; i++)
#pragma unroll
                for (int j = 0; j < 2; j++) {
                    mma16816(m_[i][j], ah[i], bh4 + j * 2);   // hi*hi
                    mma16816(m_[i][j], al[i], bh4 + j * 2);   // lo*hi
                    mma16816(m_[i][j], ah[i], bl4 + j * 2);   // hi*lo
                }
        }

        const int er = e >> 2, ec = e & 3;
        const float u0 = AT0[er], u1 = AT1[er], v0 = AT0[ec], v1 = AT1[ec];
#pragma unroll
        for (int i = 0; i < 2; i++)
#pragma unroll
            for (int j = 0; j < 2; j++)
#pragma unroll
                for (int d = 0; d < 4; d++) {
                    float m = m_[i][j][d];
                    yac[i][j][d][0] += u0 * v0 * m;
                    yac[i][j][d][1] += u0 * v1 * m;
                    yac[i][j][d][2] += u1 * v0 * m;
                    yac[i][j][d][3] += u1 * v1 * m;
                }
        __syncthreads();
    }

    // ---- scatter into bin layout as fp16 hi/lo limbs ----
#pragma unroll
    for (int i = 0; i < 2; i++) {
#pragma unroll
        for (int j = 0; j < 2; j++) {
#pragma unroll
            for (int d = 0; d < 4; d++) {
                int co = cob * 128 + mw * 32 + i * 16 + (d >> 1) * 8 + q;
                int tile = tb * 64 + nw * 16 + j * 8 + tq * 2 + (d & 1);
                int tyy = tile / 192, txx = tile - tyy * 192;
#pragma unroll
                for (int u = 0; u < 2; u++) {
#pragma unroll
                    for (int v = 0; v < 2; v++) {
                        int h = 2 * tyy + u, w = 2 * txx + v;
                        int k = (h % 3) * 3 + (w % 3);
                        size_t p   = (size_t)(h / 3) * 128 + (w / 3);
                        size_t row = (size_t)(b * 9 + k) * LPOS + p;
                        float val = yac[i][j][d][u * 2 + v];
                        __half hi = __float2half_rn(val);
                        __half lo = __float2half_rn(val - __half2float(hi));
                        if (co < CIN) {
                            g_y1h[row * CIN + co] = hi;
                            g_y1l[row * CIN + co] = lo;
                        } else {
                            g_y2h[row * COUTB + co - CIN] = hi;
                            g_y2l[row * COUTB + co - CIN] = lo;
                        }
                    }
                }
            }
        }
    }
}

// =====================================================================
// stage 2: bin GEMM, single-acc split-FP16 (R14, unchanged).
// =====================================================================
#define G2_AH  0
#define G2_AL  4352
#define G2_BH  8704
#define G2_BL  11008
#define G2_STG 13312
#define G2_SMEM (2 * G2_STG * 2)    // 53248 bytes

__global__ void __launch_bounds__(256, 2) gemm2_kernel()
{
    extern __shared__ __half s2[];
    const int t = threadIdx.x, l = t & 31, wrp = t >> 5;
    const int mw = wrp & 3, nw = wrp >> 2;
    const int q = l >> 2, tq = l & 3;
    const int s = blockIdx.x;
    const int mt = blockIdx.y >> 1, nt = blockIdx.y & 1;
    const int bk = blockIdx.z;
    const uint32_t smb = s2u(s2);

    const __half* __restrict__ Ah = g_y2h + (size_t)bk * LPOS * COUTB + mt * 128;
    const __half* __restrict__ Al = g_y2l + (size_t)bk * LPOS * COUTB + mt * 128;
    const __half* __restrict__ Bh = g_y1h + (size_t)bk * LPOS * CIN + nt * 64;
    const __half* __restrict__ Bl = g_y1l + (size_t)bk * LPOS * CIN + nt * 64;

    float acc[2][4][4];
#pragma unroll
    for (int i = 0; i < 2; i++)
#pragma unroll
        for (int j = 0; j < 4; j++)
#pragma unroll
            for (int r = 0; r < 4; r++) acc[i][j][r] = 0.f;

    auto load_chunk = [&](int p0, int buf) {
        const uint32_t base = smb + buf * (G2_STG * 2);
#pragma unroll
        for (int i = 0; i < 2; i++) {
            int id = t + i * 256;
            int row = id >> 4, kc = id & 15;
            uint32_t o = (row * 136 + kc * 8) * 2;
            size_t ga = (size_t)(p0 + row) * COUTB + kc * 8;
            cpa16(base + o,            Ah + ga);
            cpa16(base + G2_AL * 2 + o, Al + ga);
        }
        {
            int row = t >> 3, kc = t & 7;
            uint32_t o = (row * 72 + kc * 8) * 2;
            size_t gb = (size_t)(p0 + row) * CIN + kc * 8;
            cpa16(base + G2_BH * 2 + o, Bh + gb);
            cpa16(base + G2_BL * 2 + o, Bl + gb);
        }
        asm volatile("cp.async.commit_group;" ::: "memory");
    };

    const int pBase = s * (LPOS / 8);
    load_chunk(pBase, 0);

    for (int pc = 0; pc < 64; pc++) {
        const int buf = pc & 1;
        if (pc < 63) {
            load_chunk(pBase + (pc + 1) * 32, buf ^ 1);
            asm volatile("cp.async.wait_group 1;" ::: "memory");
        } else {
            asm volatile("cp.async.wait_group 0;" ::: "memory");
        }
        __syncthreads();

        const uint32_t base = smb + buf * (G2_STG * 2);
        const int r8 = l & 7, g = l >> 3;

#pragma unroll
        for (int ks = 0; ks < 2; ks++) {
            uint32_t ah[2][4], al[2][4];
#pragma unroll
            for (int i = 0; i < 2; i++) {
                uint32_t aoff = ((ks * 16 + (g >> 1) * 8 + r8) * 136
                               + mw * 32 + i * 16 + (g & 1) * 8) * 2;
                ldm4t(ah[i], base + aoff);
                ldm4t(al[i], base + G2_AL * 2 + aoff);
            }
            uint32_t bh[2][4], bl[2][4];
#pragma unroll
            for (int jp = 0; jp < 2; jp++) {
                uint32_t boff = ((ks * 16 + (g & 1) * 8 + r8) * 72
                               + nw * 32 + jp * 16 + (g >> 1) * 8) * 2;
                ldm4t(bh[jp], base + G2_BH * 2 + boff);
                ldm4t(bl[jp], base + G2_BL * 2 + boff);
            }
#pragma unroll
            for (int i = 0; i < 2; i++)
#pragma unroll
                for (int j = 0; j < 4; j++) {
                    const uint32_t* bhj = bh[j >> 1] + (j & 1) * 2;
                    const uint32_t* blj = bl[j >> 1] + (j & 1) * 2;
                    mma16816(acc[i][j], ah[i], bhj);
                    mma16816(acc[i][j], al[i], bhj);
                    mma16816(acc[i][j], ah[i], blj);
                }
        }
        __syncthreads();
    }

    float* dst = g_part + (size_t)((bk * 2 + mt) * 8 + s) * 16384;
#pragma unroll
    for (int i = 0; i < 2; i++)
#pragma unroll
        for (int j = 0; j < 4; j++)
#pragma unroll
            for (int r = 0; r < 4; r++) {
                int o  = mw * 32 + i * 16 + q + (r >> 1) * 8;
                int ii = nt * 64 + nw * 32 + j * 8 + tq * 2 + (r & 1);
                dst[(size_t)o * 128 + ii] = acc[i][j][r];
            }
}

// =====================================================================
// split-K reduce + softmax (8 splits)
// =====================================================================
__global__ void __launch_bounds__(128) softmax_kernel(float* __restrict__ out)
{
    const int bo = blockIdx.x, b = bo >> 8, o = bo & 255;
    const int mt = o >> 7, ol = o & 127, i = threadIdx.x;
    const float SCALE = 0.029462782549439476f;
    float lg[9];
#pragma unroll
    for (int k = 0; k < 9; k++) {
        const float* p = g_part + (size_t)(((b * 9 + k) * 2 + mt) * 8) * 16384 + (size_t)ol * 128 + i;
        float sum = 0.f;
#pragma unroll
        for (int s = 0; s < 8; s++) sum += p[(size_t)s * 16384];
        lg[k] = sum * SCALE;
    }
    float m = lg[0];
#pragma unroll
    for (int k = 1; k < 9; k++) m = fmaxf(m, lg[k]);
#pragma unroll
    for (int off = 16; off; off >>= 1) m = fmaxf(m, __shfl_xor_sync(0xffffffffu, m, off));
    __shared__ float smax[4];
    if ((i & 31) == 0) smax[i >> 5] = m;
    __syncthreads();
    m = fmaxf(fmaxf(smax[0], smax[1]), fmaxf(smax[2], smax[3]));
    float e[9], ls = 0.f;
#pragma unroll
    for (int k = 0; k < 9; k++) { e[k] = expf(lg[k] - m); ls += e[k]; }
#pragma unroll
    for (int off = 16; off; off >>= 1) ls += __shfl_xor_sync(0xffffffffu, ls, off);
    __shared__ float ssum[4];
    if ((i & 31) == 0) ssum[i >> 5] = ls;
    __syncthreads();
    ls = (ssum[0] + ssum[1]) + (ssum[2] + ssum[3]);
    float inv = 1.f / ls;
    float* dst = out + ((size_t)bo * 128 + i) * 9;
#pragma unroll
    for (int k = 0; k < 9; k++) dst[k] = e[k] * inv;
}

// =====================================================================
extern "C" void kernel_launch(void* const* d_in, const int* in_sizes, int n_in,
                              void* d_out, int out_size)
{
    const float* x  = (const float*)d_in[0];
    const float* w1 = (const float*)d_in[1];
    const float* w2 = (const float*)d_in[2];
    float* out = (float*)d_out;

    cudaFuncSetAttribute(wino_gemm_kernel, cudaFuncAttributeMaxDynamicSharedMemorySize, W_SMEM);
    cudaFuncSetAttribute(gemm2_kernel,     cudaFuncAttributeMaxDynamicSharedMemorySize, G2_SMEM);

    prep_uw_kernel<<<(NCO * CIN + 255) / 256, 256>>>(w1, w2);
    transform_x_kernel<<<dim3(12, 192, 8), 256>>>(x);
    wino_gemm_kernel<<<dim3(NTILE / 64, 3, NB), 512, W_SMEM>>>();
    gemm2_kernel<<<dim3(8, 4, 36), 256, G2_SMEM>>>();
    softmax_kernel<<<NB * COUTB, 128>>>(out);
}